// round 3
// baseline (speedup 1.0000x reference)
#include <cuda_runtime.h>
#include <cuda_bf16.h>
#include <cstdint>

#define DI __device__ __forceinline__

// ---------------- problem constants ----------------
constexpr int Nn = 1024;
constexpr int Ll = 2048;
constexpr int Hh = 128;
constexpr int TILES = Nn * (Ll / 128);   // 16384 (n, l-tile) pairs

// ---------------- smem layout (logits kernel) ----------------
// Tile: 128 rows x 128 bf16, row stride 272 B (17*16 -> conflict-free ldmatrix)
constexpr uint32_t TS = 128 * 272;                  // 34816
constexpr uint32_t OFF_AH0 = 0;
constexpr uint32_t OFF_AL0 = TS;
constexpr uint32_t OFF_AH1 = 2 * TS;
constexpr uint32_t OFF_AL1 = 3 * TS;
constexpr uint32_t OFF_BH  = 4 * TS;
constexpr uint32_t OFF_BL  = 5 * TS;
constexpr uint32_t OFF_QS  = 6 * TS;                // 128 floats
constexpr uint32_t OFF_WS  = OFF_QS + 512;          // 128 floats
constexpr uint32_t OFF_PS  = OFF_WS + 512;          // 128*4 floats
constexpr uint32_t SMEM_TOTAL = OFF_PS + 2048;      // 211968 B

// ---------------- scratch (__device__ globals; no allocations) -------------
__device__ float g_state[Nn * Hh];
__device__ float g_q[Nn * Hh];
__device__ float g_logits[Nn * Ll];
__device__ int   g_idx[Nn];

// ---------------- helpers ----------------
DI uint32_t smem_u32(const void* p) {
    uint32_t a;
    asm("{ .reg .u64 t; cvta.to.shared.u64 t, %1; cvt.u32.u64 %0, t; }" : "=r"(a) : "l"(p));
    return a;
}

DI void ldsm4(uint32_t* r, uint32_t a) {
    asm volatile("ldmatrix.sync.aligned.m8n8.x4.shared.b16 {%0,%1,%2,%3}, [%4];"
                 : "=r"(r[0]), "=r"(r[1]), "=r"(r[2]), "=r"(r[3]) : "r"(a));
}

DI void mma_bf16(float* c, const uint32_t* a, const uint32_t* b) {
    asm volatile(
        "mma.sync.aligned.m16n8k16.row.col.f32.bf16.bf16.f32 "
        "{%0,%1,%2,%3}, {%4,%5,%6,%7}, {%8,%9}, {%0,%1,%2,%3};"
        : "+f"(c[0]), "+f"(c[1]), "+f"(c[2]), "+f"(c[3])
        : "r"(a[0]), "r"(a[1]), "r"(a[2]), "r"(a[3]), "r"(b[0]), "r"(b[1]));
}

// accurate-enough activations (MUFU EX2+RCP, ~1e-7 abs)
DI float tanh_acc(float x) {
    float e;
    asm("ex2.approx.f32 %0, %1;" : "=f"(e) : "f"(x * 2.8853900817779268f)); // 2*log2(e)
    float r;
    asm("rcp.approx.f32 %0, %1;" : "=f"(r) : "f"(e + 1.0f));
    return fmaf(-2.0f, r, 1.0f);
}
DI float sigmoid_acc(float x) {
    float e;
    asm("ex2.approx.f32 %0, %1;" : "=f"(e) : "f"(-x * 1.4426950408889634f));
    float r;
    asm("rcp.approx.f32 %0, %1;" : "=f"(r) : "f"(e + 1.0f));
    return r;
}
DI float ex2(float x) {
    float e;
    asm("ex2.approx.f32 %0, %1;" : "=f"(e) : "f"(x));
    return e;
}

// ---- tile staging: 256 threads; thread t -> row t&127, col-half t>>7 -------
DI void load_tile_regs(const float* __restrict__ src, float4* v, int tid) {
    int row = tid & 127, half = tid >> 7;
    const float4* s = reinterpret_cast<const float4*>(src) + row * 32 + half * 16;
#pragma unroll
    for (int j = 0; j < 16; ++j) v[j] = __ldg(s + j);
}

DI void store_tile_smem(const float4* v, char* smem, uint32_t oh, uint32_t ol, int tid) {
    int row = tid & 127, half = tid >> 7;
    uint32_t rb = (uint32_t)row * 272 + (uint32_t)half * 128;
#pragma unroll
    for (int j = 0; j < 16; ++j) {
        float4 x = v[j];
        __nv_bfloat16 h0 = __float2bfloat16_rn(x.x);
        __nv_bfloat16 h1 = __float2bfloat16_rn(x.y);
        __nv_bfloat16 h2 = __float2bfloat16_rn(x.z);
        __nv_bfloat16 h3 = __float2bfloat16_rn(x.w);
        uint32_t hp0 = ((uint32_t)__bfloat16_as_ushort(h1) << 16) | __bfloat16_as_ushort(h0);
        uint32_t hp1 = ((uint32_t)__bfloat16_as_ushort(h3) << 16) | __bfloat16_as_ushort(h2);
        __nv_bfloat16 l0 = __float2bfloat16_rn(x.x - __bfloat162float(h0));
        __nv_bfloat16 l1 = __float2bfloat16_rn(x.y - __bfloat162float(h1));
        __nv_bfloat16 l2 = __float2bfloat16_rn(x.z - __bfloat162float(h2));
        __nv_bfloat16 l3 = __float2bfloat16_rn(x.w - __bfloat162float(h3));
        uint32_t lp0 = ((uint32_t)__bfloat16_as_ushort(l1) << 16) | __bfloat16_as_ushort(l0);
        uint32_t lp1 = ((uint32_t)__bfloat16_as_ushort(l3) << 16) | __bfloat16_as_ushort(l2);
        uint32_t off = rb + (uint32_t)j * 8;
        *reinterpret_cast<uint2*>(smem + oh + off) = make_uint2(hp0, hp1);
        *reinterpret_cast<uint2*>(smem + ol + off) = make_uint2(lp0, lp1);
    }
}

// =====================================================================
// GRU cell + q = state' @ Wq^T.   One CTA per n, 128 threads.
// =====================================================================
__global__ void gru_q_kernel(const float* __restrict__ ei,
                             const float* __restrict__ st_in,
                             const float* __restrict__ W_ih, const float* __restrict__ W_hh,
                             const float* __restrict__ b_ih, const float* __restrict__ b_hh,
                             const float* __restrict__ Wq, int step) {
    __shared__ float xs[128], hs[128], ss[128];
    int n = blockIdx.x, t = threadIdx.x;
    if (step == 0) {
        xs[t] = 1.0f;
        hs[t] = st_in[n * 128 + t];
    } else {
        int j = g_idx[n];
        xs[t] = ei[((size_t)n * Ll + j) * Hh + t];
        hs[t] = g_state[n * 128 + t];
    }
    __syncthreads();
    const float4* x4 = reinterpret_cast<const float4*>(xs);
    const float4* h4 = reinterpret_cast<const float4*>(hs);
    const float4* Wi = reinterpret_cast<const float4*>(W_ih);
    const float4* Wh = reinterpret_cast<const float4*>(W_hh);
    float rx = 0, zx = 0, nx = 0, rh = 0, zh = 0, nh = 0;
#pragma unroll 4
    for (int k = 0; k < 32; ++k) {
        float4 xv = x4[k], hv = h4[k];
        float4 w;
        w = __ldg(&Wi[(t      ) * 32 + k]); rx += xv.x*w.x + xv.y*w.y + xv.z*w.z + xv.w*w.w;
        w = __ldg(&Wi[(t + 128) * 32 + k]); zx += xv.x*w.x + xv.y*w.y + xv.z*w.z + xv.w*w.w;
        w = __ldg(&Wi[(t + 256) * 32 + k]); nx += xv.x*w.x + xv.y*w.y + xv.z*w.z + xv.w*w.w;
        w = __ldg(&Wh[(t      ) * 32 + k]); rh += hv.x*w.x + hv.y*w.y + hv.z*w.z + hv.w*w.w;
        w = __ldg(&Wh[(t + 128) * 32 + k]); zh += hv.x*w.x + hv.y*w.y + hv.z*w.z + hv.w*w.w;
        w = __ldg(&Wh[(t + 256) * 32 + k]); nh += hv.x*w.x + hv.y*w.y + hv.z*w.z + hv.w*w.w;
    }
    float r  = sigmoid_acc(rx + b_ih[t]       + rh + b_hh[t]);
    float z  = sigmoid_acc(zx + b_ih[128 + t] + zh + b_hh[128 + t]);
    float nn = tanh_acc(nx + b_ih[256 + t] + r * (nh + b_hh[256 + t]));
    float hp = (1.0f - z) * nn + z * hs[t];
    g_state[n * 128 + t] = hp;
    ss[t] = hp;
    __syncthreads();
    const float4* s4  = reinterpret_cast<const float4*>(ss);
    const float4* Wq4 = reinterpret_cast<const float4*>(Wq);
    float qv = 0;
#pragma unroll 4
    for (int k = 0; k < 32; ++k) {
        float4 sv = s4[k], w = __ldg(&Wq4[t * 32 + k]);
        qv += sv.x*w.x + sv.y*w.y + sv.z*w.z + sv.w*w.w;
    }
    g_q[n * 128 + t] = qv;
}

// =====================================================================
// Fused logits: per (n, l-tile): D = eo_tile @ Wk^T (bf16x3 HMMA, fp32 acc),
// logits[l] = sum_o w[o]*tanh(q[n,o] + D[l,o]).
// Persistent CTAs, 256 threads (8 warps, 2x4 grid, 64x32 warp tiles).
// =====================================================================
__global__ void __launch_bounds__(256, 1)
logits_kernel(const float* __restrict__ eo, const float* __restrict__ wk,
              const float* __restrict__ wscore) {
    extern __shared__ char smem[];
    uint32_t sb = smem_u32(smem);
    int tid = threadIdx.x;
    int wid = tid >> 5, lane = tid & 31;
    int wm = wid >> 2, wn = wid & 3;          // 2 x 4 warp grid

    float* qs = reinterpret_cast<float*>(smem + OFF_QS);
    float* ws = reinterpret_cast<float*>(smem + OFF_WS);
    float* ps = reinterpret_cast<float*>(smem + OFF_PS);

    float4 v[16];

    // B = Wk hi/lo, loaded once
    load_tile_regs(wk, v, tid);
    store_tile_smem(v, smem, OFF_BH, OFF_BL, tid);
    if (tid < 128) ws[tid] = wscore[tid];

    // prologue: stage first tile
    int tile = blockIdx.x;
    int grid = gridDim.x;
    if (tile < TILES) {
        const float* src = eo + ((size_t)(tile >> 4) * Ll + (tile & 15) * 128) * Hh;
        load_tile_regs(src, v, tid);
        store_tile_smem(v, smem, OFF_AH0, OFF_AL0, tid);
    }
    __syncthreads();

    // per-lane ldmatrix row offsets (within a tile)
    int ra = lane & 7, qa = lane >> 3;
    uint32_t a_off[4], b_off[2];
#pragma unroll
    for (int mi = 0; mi < 4; ++mi)
        a_off[mi] = (uint32_t)((wm * 64 + mi * 16 + (qa & 1) * 8 + ra) * 272 + (qa >> 1) * 16);
#pragma unroll
    for (int p = 0; p < 2; ++p)
        b_off[p] = (uint32_t)((wn * 32 + p * 16 + ((lane >> 4) & 1) * 8 + ra) * 272 +
                              ((lane >> 3) & 1) * 16);

    int cur = 0;
    for (; tile < TILES; tile += grid) {
        int n = tile >> 4, lt = tile & 15;
        if (tid < 128) qs[tid] = g_q[n * 128 + tid];

        // stage next tile into registers (LDGs in flight during mainloop)
        int nt = (tile + grid < TILES) ? tile + grid : tile;
        const float* nsrc = eo + ((size_t)(nt >> 4) * Ll + (nt & 15) * 128) * Hh;
        load_tile_regs(nsrc, v, tid);

        uint32_t aAh = sb + (cur ? OFF_AH1 : OFF_AH0);
        uint32_t aAl = sb + (cur ? OFF_AL1 : OFF_AL0);
        uint32_t aBh = sb + OFF_BH, aBl = sb + OFF_BL;

        float C[4][4][4];
#pragma unroll
        for (int mi = 0; mi < 4; ++mi)
#pragma unroll
            for (int ni = 0; ni < 4; ++ni)
#pragma unroll
                for (int r = 0; r < 4; ++r) C[mi][ni][r] = 0.0f;

#pragma unroll
        for (int ks = 0; ks < 8; ++ks) {
            uint32_t kb = (uint32_t)ks * 32;
            uint32_t Ah[4][4], Al[4][4], Bh[4][2], Bl[4][2];
#pragma unroll
            for (int mi = 0; mi < 4; ++mi) {
                ldsm4(Ah[mi], aAh + a_off[mi] + kb);
                ldsm4(Al[mi], aAl + a_off[mi] + kb);
            }
#pragma unroll
            for (int p = 0; p < 2; ++p) {
                uint32_t r4[4];
                ldsm4(r4, aBh + b_off[p] + kb);
                Bh[2*p][0] = r4[0]; Bh[2*p][1] = r4[1];
                Bh[2*p+1][0] = r4[2]; Bh[2*p+1][1] = r4[3];
                ldsm4(r4, aBl + b_off[p] + kb);
                Bl[2*p][0] = r4[0]; Bl[2*p][1] = r4[1];
                Bl[2*p+1][0] = r4[2]; Bl[2*p+1][1] = r4[3];
            }
#pragma unroll
            for (int mi = 0; mi < 4; ++mi)
#pragma unroll
                for (int ni = 0; ni < 4; ++ni) {
                    mma_bf16(C[mi][ni], Ah[mi], Bh[ni]);
                    mma_bf16(C[mi][ni], Al[mi], Bh[ni]);
                    mma_bf16(C[mi][ni], Ah[mi], Bl[ni]);
                }
        }
        __syncthreads();   // mainloop done in all warps; qs visible

        // ---- epilogue: tanh + weighted sum, reduce over o ----
        int t4 = lane >> 2, tm = lane & 3;
#pragma unroll
        for (int mi = 0; mi < 4; ++mi) {
            float s0 = 0.0f, s1 = 0.0f;
#pragma unroll
            for (int ni = 0; ni < 4; ++ni) {
                int o = wn * 32 + ni * 8 + tm * 2;
                float w0 = ws[o], w1 = ws[o + 1];
                float q0 = qs[o], q1 = qs[o + 1];
                s0 += w0 * tanh_acc(q0 + C[mi][ni][0]) + w1 * tanh_acc(q1 + C[mi][ni][1]);
                s1 += w0 * tanh_acc(q0 + C[mi][ni][2]) + w1 * tanh_acc(q1 + C[mi][ni][3]);
            }
            s0 += __shfl_xor_sync(0xffffffff, s0, 1);
            s0 += __shfl_xor_sync(0xffffffff, s0, 2);
            s1 += __shfl_xor_sync(0xffffffff, s1, 1);
            s1 += __shfl_xor_sync(0xffffffff, s1, 2);
            if (tm == 0) {
                int r0 = wm * 64 + mi * 16 + t4;
                ps[r0 * 4 + wn] = s0;
                ps[(r0 + 8) * 4 + wn] = s1;
            }
        }

        // stage next tile into the other buffer
        store_tile_smem(v, smem, cur ? OFF_AH0 : OFF_AH1, cur ? OFF_AL0 : OFF_AL1, tid);
        __syncthreads();   // ps + next-buffer stores visible

        if (tid < 128) {
            float* p = ps + tid * 4;
            g_logits[(size_t)n * Ll + lt * 128 + tid] = p[0] + p[1] + p[2] + p[3];
        }
        cur ^= 1;
    }
}

// =====================================================================
// Softmax over L per row + first-max argmax (jnp.argmax semantics).
// =====================================================================
__global__ void softmax_kernel(float* __restrict__ out, int step) {
    __shared__ float sv[256];
    __shared__ int   si[256];
    __shared__ float ssum[256];
    int n = blockIdx.x, t = threadIdx.x;
    const float* lg = g_logits + (size_t)n * Ll;
    float v[8];
    float bv = -3.4e38f;
    int bi = 0x7fffffff;
#pragma unroll
    for (int j = 0; j < 8; ++j) {
        int i = t + j * 256;
        v[j] = lg[i];
        if (v[j] > bv) { bv = v[j]; bi = i; }   // strict > keeps first index
    }
    sv[t] = bv; si[t] = bi;
    __syncthreads();
    for (int s = 128; s; s >>= 1) {
        if (t < s) {
            float ov = sv[t + s]; int oi = si[t + s];
            if (ov > sv[t] || (ov == sv[t] && oi < si[t])) { sv[t] = ov; si[t] = oi; }
        }
        __syncthreads();
    }
    float m = sv[0];
    if (t == 0) g_idx[n] = si[0];
    float e[8];
    float lsum = 0.0f;
#pragma unroll
    for (int j = 0; j < 8; ++j) {
        e[j] = ex2((v[j] - m) * 1.4426950408889634f);
        lsum += e[j];
    }
    ssum[t] = lsum;
    __syncthreads();
    for (int s = 128; s; s >>= 1) {
        if (t < s) ssum[t] += ssum[t + s];
        __syncthreads();
    }
    float inv = 1.0f / ssum[0];
    float* o = out + ((size_t)n * 2 + step) * Ll;
#pragma unroll
    for (int j = 0; j < 8; ++j) o[t + j * 256] = e[j] * inv;
}

// =====================================================================
extern "C" void kernel_launch(void* const* d_in, const int* in_sizes, int n_in,
                              void* d_out, int out_size) {
    const float* encoder_input  = (const float*)d_in[0];
    const float* encoder_output = (const float*)d_in[1];
    const float* state          = (const float*)d_in[2];
    const float* W_ih           = (const float*)d_in[3];
    const float* W_hh           = (const float*)d_in[4];
    const float* b_ih           = (const float*)d_in[5];
    const float* b_hh           = (const float*)d_in[6];
    const float* Wq             = (const float*)d_in[7];
    const float* Wk             = (const float*)d_in[8];
    const float* w_score        = (const float*)d_in[9];
    float* out = (float*)d_out;

    cudaFuncSetAttribute(logits_kernel, cudaFuncAttributeMaxDynamicSharedMemorySize,
                         SMEM_TOTAL);
    int nsm = 148;
    cudaDeviceGetAttribute(&nsm, cudaDevAttrMultiProcessorCount, 0);

    // step 0
    gru_q_kernel<<<Nn, 128>>>(encoder_input, state, W_ih, W_hh, b_ih, b_hh, Wq, 0);
    logits_kernel<<<nsm, 256, SMEM_TOTAL>>>(encoder_output, Wk, w_score);
    softmax_kernel<<<Nn, 256>>>(out, 0);
    // step 1
    gru_q_kernel<<<Nn, 128>>>(encoder_input, state, W_ih, W_hh, b_ih, b_hh, Wq, 1);
    logits_kernel<<<nsm, 256, SMEM_TOTAL>>>(encoder_output, Wk, w_score);
    softmax_kernel<<<Nn, 256>>>(out, 1);
}

// round 5
// speedup vs baseline: 1.4851x; 1.4851x over previous
#include <cuda_runtime.h>
#include <cuda_bf16.h>
#include <cuda_fp16.h>
#include <cstdint>

#define DI __device__ __forceinline__

// ---------------- problem constants ----------------
constexpr int Nn = 1024;
constexpr int Ll = 2048;
constexpr int Hh = 128;
constexpr int TILES = Nn * (Ll / 128);   // 16384 (n, l-tile) pairs

// ---------------- smem layout (logits kernel) ----------------
// Tile: 128 rows x 128 bf16, row stride 272 B (17*16 -> conflict-free ldmatrix)
constexpr uint32_t TS = 128 * 272;                  // 34816
constexpr uint32_t OFF_AH0 = 0;
constexpr uint32_t OFF_AL0 = TS;
constexpr uint32_t OFF_AH1 = 2 * TS;
constexpr uint32_t OFF_AL1 = 3 * TS;
constexpr uint32_t OFF_BH  = 4 * TS;
constexpr uint32_t OFF_BL  = 5 * TS;
constexpr uint32_t OFF_QS  = 6 * TS;                // 128 floats
constexpr uint32_t OFF_WS  = OFF_QS + 512;          // 128 floats
constexpr uint32_t OFF_PS  = OFF_WS + 512;          // 128*4 floats
constexpr uint32_t SMEM_TOTAL = OFF_PS + 2048;      // 211968 B

// ---------------- scratch (__device__ globals; no allocations) -------------
__device__ float  g_state[Nn * Hh];
__device__ float  g_q[Nn * Hh];
__device__ float  g_logits[Nn * Ll];
__device__ int    g_idx[Nn];
__device__ __half g_k[(size_t)Nn * Ll * Hh];   // 512 MB: k = eo @ Wk^T, fp16

// ---------------- helpers ----------------
DI uint32_t smem_u32(const void* p) {
    uint32_t a;
    asm("{ .reg .u64 t; cvta.to.shared.u64 t, %1; cvt.u32.u64 %0, t; }" : "=r"(a) : "l"(p));
    return a;
}

DI void ldsm4(uint32_t* r, uint32_t a) {
    asm volatile("ldmatrix.sync.aligned.m8n8.x4.shared.b16 {%0,%1,%2,%3}, [%4];"
                 : "=r"(r[0]), "=r"(r[1]), "=r"(r[2]), "=r"(r[3]) : "r"(a));
}

DI void mma_bf16(float* c, const uint32_t* a, const uint32_t* b) {
    asm volatile(
        "mma.sync.aligned.m16n8k16.row.col.f32.bf16.bf16.f32 "
        "{%0,%1,%2,%3}, {%4,%5,%6,%7}, {%8,%9}, {%0,%1,%2,%3};"
        : "+f"(c[0]), "+f"(c[1]), "+f"(c[2]), "+f"(c[3])
        : "r"(a[0]), "r"(a[1]), "r"(a[2]), "r"(a[3]), "r"(b[0]), "r"(b[1]));
}

// accurate activations (MUFU EX2+RCP, ~1e-7 abs)
DI float tanh_acc(float x) {
    float e;
    asm("ex2.approx.f32 %0, %1;" : "=f"(e) : "f"(x * 2.8853900817779268f)); // 2*log2(e)
    float r;
    asm("rcp.approx.f32 %0, %1;" : "=f"(r) : "f"(e + 1.0f));
    return fmaf(-2.0f, r, 1.0f);
}
DI float sigmoid_acc(float x) {
    float e;
    asm("ex2.approx.f32 %0, %1;" : "=f"(e) : "f"(-x * 1.4426950408889634f));
    float r;
    asm("rcp.approx.f32 %0, %1;" : "=f"(r) : "f"(e + 1.0f));
    return r;
}
DI float ex2(float x) {
    float e;
    asm("ex2.approx.f32 %0, %1;" : "=f"(e) : "f"(x));
    return e;
}

// ---- tile staging for GEMM: 256 threads; thread t -> row t&127, half t>>7 --
DI void load_tile_regs(const float* __restrict__ src, float4* v, int tid) {
    int row = tid & 127, half = tid >> 7;
    const float4* s = reinterpret_cast<const float4*>(src) + row * 32 + half * 16;
#pragma unroll
    for (int j = 0; j < 16; ++j) v[j] = __ldg(s + j);
}

DI void store_tile_smem(const float4* v, char* smem, uint32_t oh, uint32_t ol, int tid) {
    int row = tid & 127, half = tid >> 7;
    uint32_t rb = (uint32_t)row * 272 + (uint32_t)half * 128;
#pragma unroll
    for (int j = 0; j < 16; ++j) {
        float4 x = v[j];
        __nv_bfloat16 h0 = __float2bfloat16_rn(x.x);
        __nv_bfloat16 h1 = __float2bfloat16_rn(x.y);
        __nv_bfloat16 h2 = __float2bfloat16_rn(x.z);
        __nv_bfloat16 h3 = __float2bfloat16_rn(x.w);
        uint32_t hp0 = ((uint32_t)__bfloat16_as_ushort(h1) << 16) | __bfloat16_as_ushort(h0);
        uint32_t hp1 = ((uint32_t)__bfloat16_as_ushort(h3) << 16) | __bfloat16_as_ushort(h2);
        __nv_bfloat16 l0 = __float2bfloat16_rn(x.x - __bfloat162float(h0));
        __nv_bfloat16 l1 = __float2bfloat16_rn(x.y - __bfloat162float(h1));
        __nv_bfloat16 l2 = __float2bfloat16_rn(x.z - __bfloat162float(h2));
        __nv_bfloat16 l3 = __float2bfloat16_rn(x.w - __bfloat162float(h3));
        uint32_t lp0 = ((uint32_t)__bfloat16_as_ushort(l1) << 16) | __bfloat16_as_ushort(l0);
        uint32_t lp1 = ((uint32_t)__bfloat16_as_ushort(l3) << 16) | __bfloat16_as_ushort(l2);
        uint32_t off = rb + (uint32_t)j * 8;
        *reinterpret_cast<uint2*>(smem + oh + off) = make_uint2(hp0, hp1);
        *reinterpret_cast<uint2*>(smem + ol + off) = make_uint2(lp0, lp1);
    }
}

// =====================================================================
// GRU cell + q = state' @ Wq^T.   4 n per CTA, 128 threads, coalesced
// weight loads (lane-major float4) + shuffle reduction.
// =====================================================================
__global__ void __launch_bounds__(128)
gru_q_kernel(const float* __restrict__ ei,
             const float* __restrict__ st_in,
             const float* __restrict__ W_ih, const float* __restrict__ W_hh,
             const float* __restrict__ b_ih, const float* __restrict__ b_hh,
             const float* __restrict__ Wq, int step) {
    __shared__ float xs[4][128], hs[4][128], ss[4][128];
    __shared__ float ax[4][384], ah[4][384];
    int t = threadIdx.x, w = t >> 5, lane = t & 31;
    int n0 = blockIdx.x * 4;

#pragma unroll
    for (int j = 0; j < 4; ++j) {
        int n = n0 + j;
        if (step == 0) {
            xs[j][t] = 1.0f;
            hs[j][t] = st_in[n * 128 + t];
        } else {
            int ix = g_idx[n];
            xs[j][t] = ei[((size_t)n * Ll + ix) * Hh + t];
            hs[j][t] = g_state[n * 128 + t];
        }
    }
    __syncthreads();

    const float4* Wi4 = reinterpret_cast<const float4*>(W_ih);
    const float4* Wh4 = reinterpret_cast<const float4*>(W_hh);
#pragma unroll 2
    for (int i = 0; i < 96; ++i) {
        int o = w + 4 * i;
        float4 wi = __ldg(&Wi4[o * 32 + lane]);
        float4 wh = __ldg(&Wh4[o * 32 + lane]);
        float sx[4], sh[4];
#pragma unroll
        for (int j = 0; j < 4; ++j) {
            float4 xv = reinterpret_cast<const float4*>(xs[j])[lane];
            float4 hv = reinterpret_cast<const float4*>(hs[j])[lane];
            sx[j] = wi.x*xv.x + wi.y*xv.y + wi.z*xv.z + wi.w*xv.w;
            sh[j] = wh.x*hv.x + wh.y*hv.y + wh.z*hv.z + wh.w*hv.w;
        }
#pragma unroll
        for (int d = 16; d; d >>= 1)
#pragma unroll
            for (int j = 0; j < 4; ++j) {
                sx[j] += __shfl_xor_sync(0xffffffff, sx[j], d);
                sh[j] += __shfl_xor_sync(0xffffffff, sh[j], d);
            }
        if (lane == 0)
#pragma unroll
            for (int j = 0; j < 4; ++j) { ax[j][o] = sx[j]; ah[j][o] = sh[j]; }
    }
    __syncthreads();

#pragma unroll
    for (int j = 0; j < 4; ++j) {
        float r  = sigmoid_acc(ax[j][t]       + b_ih[t]       + ah[j][t]       + b_hh[t]);
        float z  = sigmoid_acc(ax[j][128 + t] + b_ih[128 + t] + ah[j][128 + t] + b_hh[128 + t]);
        float nn = tanh_acc(ax[j][256 + t] + b_ih[256 + t] +
                            r * (ah[j][256 + t] + b_hh[256 + t]));
        float hp = (1.0f - z) * nn + z * hs[j][t];
        g_state[(n0 + j) * 128 + t] = hp;
        ss[j][t] = hp;
    }
    __syncthreads();

    const float4* Wq4 = reinterpret_cast<const float4*>(Wq);
#pragma unroll 2
    for (int i = 0; i < 32; ++i) {
        int o = w + 4 * i;
        float4 wv = __ldg(&Wq4[o * 32 + lane]);
        float s[4];
#pragma unroll
        for (int j = 0; j < 4; ++j) {
            float4 sv = reinterpret_cast<const float4*>(ss[j])[lane];
            s[j] = wv.x*sv.x + wv.y*sv.y + wv.z*sv.z + wv.w*sv.w;
        }
#pragma unroll
        for (int d = 16; d; d >>= 1)
#pragma unroll
            for (int j = 0; j < 4; ++j) s[j] += __shfl_xor_sync(0xffffffff, s[j], d);
        if (lane == 0)
#pragma unroll
            for (int j = 0; j < 4; ++j) g_q[(n0 + j) * 128 + o] = s[j];
    }
}

// =====================================================================
// Launch B: D = eo_tile @ Wk^T (bf16x3 HMMA, fp32 acc); writes k (fp16)
// AND step-1 logits = sum_o w[o]*tanh(q0[n,o] + D[l,o]).
// Persistent CTAs, 256 threads (8 warps, 2x4 grid, 64x32 warp tiles).
// =====================================================================
__global__ void __launch_bounds__(256, 1)
logits_k_kernel(const float* __restrict__ eo, const float* __restrict__ wk,
                const float* __restrict__ wscore) {
    extern __shared__ char smem[];
    uint32_t sb = smem_u32(smem);
    int tid = threadIdx.x;
    int wid = tid >> 5, lane = tid & 31;
    int wm = wid >> 2, wn = wid & 3;          // 2 x 4 warp grid

    float* qs = reinterpret_cast<float*>(smem + OFF_QS);
    float* ws = reinterpret_cast<float*>(smem + OFF_WS);
    float* ps = reinterpret_cast<float*>(smem + OFF_PS);

    float4 v[16];

    load_tile_regs(wk, v, tid);
    store_tile_smem(v, smem, OFF_BH, OFF_BL, tid);
    if (tid < 128) ws[tid] = wscore[tid];

    int tile = blockIdx.x;
    int grid = gridDim.x;
    if (tile < TILES) {
        const float* src = eo + ((size_t)(tile >> 4) * Ll + (tile & 15) * 128) * Hh;
        load_tile_regs(src, v, tid);
        store_tile_smem(v, smem, OFF_AH0, OFF_AL0, tid);
    }
    __syncthreads();

    int ra = lane & 7, qa = lane >> 3;
    uint32_t a_off[4], b_off[2];
#pragma unroll
    for (int mi = 0; mi < 4; ++mi)
        a_off[mi] = (uint32_t)((wm * 64 + mi * 16 + (qa & 1) * 8 + ra) * 272 + (qa >> 1) * 16);
#pragma unroll
    for (int p = 0; p < 2; ++p)
        b_off[p] = (uint32_t)((wn * 32 + p * 16 + ((lane >> 4) & 1) * 8 + ra) * 272 +
                              ((lane >> 3) & 1) * 16);

    int cur = 0;
    for (; tile < TILES; tile += grid) {
        int n = tile >> 4, lt = tile & 15;
        if (tid < 128) qs[tid] = g_q[n * 128 + tid];

        int nt = (tile + grid < TILES) ? tile + grid : tile;
        const float* nsrc = eo + ((size_t)(nt >> 4) * Ll + (nt & 15) * 128) * Hh;
        load_tile_regs(nsrc, v, tid);

        uint32_t aAh = sb + (cur ? OFF_AH1 : OFF_AH0);
        uint32_t aAl = sb + (cur ? OFF_AL1 : OFF_AL0);
        uint32_t aBh = sb + OFF_BH, aBl = sb + OFF_BL;

        float C[4][4][4];
#pragma unroll
        for (int mi = 0; mi < 4; ++mi)
#pragma unroll
            for (int ni = 0; ni < 4; ++ni)
#pragma unroll
                for (int r = 0; r < 4; ++r) C[mi][ni][r] = 0.0f;

#pragma unroll
        for (int ks = 0; ks < 8; ++ks) {
            uint32_t kb = (uint32_t)ks * 32;
            uint32_t Ah[4][4], Al[4][4], Bh[4][2], Bl[4][2];
#pragma unroll
            for (int mi = 0; mi < 4; ++mi) {
                ldsm4(Ah[mi], aAh + a_off[mi] + kb);
                ldsm4(Al[mi], aAl + a_off[mi] + kb);
            }
#pragma unroll
            for (int p = 0; p < 2; ++p) {
                uint32_t r4[4];
                ldsm4(r4, aBh + b_off[p] + kb);
                Bh[2*p][0] = r4[0]; Bh[2*p][1] = r4[1];
                Bh[2*p+1][0] = r4[2]; Bh[2*p+1][1] = r4[3];
                ldsm4(r4, aBl + b_off[p] + kb);
                Bl[2*p][0] = r4[0]; Bl[2*p][1] = r4[1];
                Bl[2*p+1][0] = r4[2]; Bl[2*p+1][1] = r4[3];
            }
#pragma unroll
            for (int mi = 0; mi < 4; ++mi)
#pragma unroll
                for (int ni = 0; ni < 4; ++ni) {
                    mma_bf16(C[mi][ni], Ah[mi], Bh[ni]);
                    mma_bf16(C[mi][ni], Al[mi], Bh[ni]);
                    mma_bf16(C[mi][ni], Ah[mi], Bl[ni]);
                }
        }
        __syncthreads();   // mainloop done; qs visible

        // ---- write k tile (fp16) + tanh/dot epilogue ----
        __half* kb = g_k + ((size_t)n * Ll + lt * 128) * Hh;
        int t4 = lane >> 2, tm = lane & 3;
#pragma unroll
        for (int mi = 0; mi < 4; ++mi) {
            int r0 = wm * 64 + mi * 16 + t4;
            float s0 = 0.0f, s1 = 0.0f;
#pragma unroll
            for (int ni = 0; ni < 4; ++ni) {
                int o = wn * 32 + ni * 8 + tm * 2;
                *reinterpret_cast<__half2*>(kb + (size_t)r0 * Hh + o) =
                    __floats2half2_rn(C[mi][ni][0], C[mi][ni][1]);
                *reinterpret_cast<__half2*>(kb + (size_t)(r0 + 8) * Hh + o) =
                    __floats2half2_rn(C[mi][ni][2], C[mi][ni][3]);
                float w0 = ws[o], w1 = ws[o + 1];
                float q0 = qs[o], q1 = qs[o + 1];
                s0 += w0 * tanh_acc(q0 + C[mi][ni][0]) + w1 * tanh_acc(q1 + C[mi][ni][1]);
                s1 += w0 * tanh_acc(q0 + C[mi][ni][2]) + w1 * tanh_acc(q1 + C[mi][ni][3]);
            }
            s0 += __shfl_xor_sync(0xffffffff, s0, 1);
            s0 += __shfl_xor_sync(0xffffffff, s0, 2);
            s1 += __shfl_xor_sync(0xffffffff, s1, 1);
            s1 += __shfl_xor_sync(0xffffffff, s1, 2);
            if (tm == 0) {
                ps[r0 * 4 + wn] = s0;
                ps[(r0 + 8) * 4 + wn] = s1;
            }
        }

        store_tile_smem(v, smem, cur ? OFF_AH0 : OFF_AH1, cur ? OFF_AL0 : OFF_AL1, tid);
        __syncthreads();

        if (tid < 128) {
            float* p = ps + tid * 4;
            g_logits[(size_t)n * Ll + lt * 128 + tid] = p[0] + p[1] + p[2] + p[3];
        }
        cur ^= 1;
    }
}

// =====================================================================
// Step-1 softmax + first-max argmax (jnp.argmax semantics).
// =====================================================================
__global__ void softmax_kernel(float* __restrict__ out, int step) {
    __shared__ float sv[256];
    __shared__ int   si[256];
    __shared__ float ssum[256];
    int n = blockIdx.x, t = threadIdx.x;
    const float* lg = g_logits + (size_t)n * Ll;
    float v[8];
    float bv = -3.4e38f;
    int bi = 0x7fffffff;
#pragma unroll
    for (int j = 0; j < 8; ++j) {
        int i = t + j * 256;
        v[j] = lg[i];
        if (v[j] > bv) { bv = v[j]; bi = i; }   // strict > keeps first index
    }
    sv[t] = bv; si[t] = bi;
    __syncthreads();
    for (int s = 128; s; s >>= 1) {
        if (t < s) {
            float ov = sv[t + s]; int oi = si[t + s];
            if (ov > sv[t] || (ov == sv[t] && oi < si[t])) { sv[t] = ov; si[t] = oi; }
        }
        __syncthreads();
    }
    float m = sv[0];
    if (t == 0) g_idx[n] = si[0];
    float e[8];
    float lsum = 0.0f;
#pragma unroll
    for (int j = 0; j < 8; ++j) {
        e[j] = ex2((v[j] - m) * 1.4426950408889634f);
        lsum += e[j];
    }
    ssum[t] = lsum;
    __syncthreads();
    for (int s = 128; s; s >>= 1) {
        if (t < s) ssum[t] += ssum[t + s];
        __syncthreads();
    }
    float inv = 1.0f / ssum[0];
    float* o = out + ((size_t)n * 2 + step) * Ll;
#pragma unroll
    for (int j = 0; j < 8; ++j) o[t + j * 256] = e[j] * inv;
}

// =====================================================================
// Launch C: step-2 scores. Streams k (fp16), logits + fused softmax.
// One CTA per n, 256 threads (8 warps; warp per l-row, strided).
// =====================================================================
__global__ void __launch_bounds__(256)
score2_kernel(float* __restrict__ out, const float* __restrict__ wscore) {
    __shared__ float qs[128], ws[128];
    __shared__ float lg[2048];
    __shared__ float red[8];
    int n = blockIdx.x, t = threadIdx.x, w = t >> 5, lane = t & 31;

    if (t < 128) { qs[t] = g_q[n * 128 + t]; ws[t] = wscore[t]; }
    __syncthreads();

    // row l: 128 halves = 32 lanes x uint2 (4 halves each)
    const uint2* kp = reinterpret_cast<const uint2*>(g_k + (size_t)n * Ll * Hh);
    float4 wv = reinterpret_cast<const float4*>(ws)[lane];
    float4 qv = reinterpret_cast<const float4*>(qs)[lane];
    for (int l = w; l < Ll; l += 8) {
        uint2 kr = __ldg(&kp[l * 32 + lane]);
        __half2 k01 = *reinterpret_cast<__half2*>(&kr.x);
        __half2 k23 = *reinterpret_cast<__half2*>(&kr.y);
        float s = wv.x * tanh_acc(qv.x + __low2float(k01)) +
                  wv.y * tanh_acc(qv.y + __high2float(k01)) +
                  wv.z * tanh_acc(qv.z + __low2float(k23)) +
                  wv.w * tanh_acc(qv.w + __high2float(k23));
#pragma unroll
        for (int d = 16; d; d >>= 1) s += __shfl_xor_sync(0xffffffff, s, d);
        if (lane == 0) lg[l] = s;
    }
    __syncthreads();

    float v[8];
    float m = -3.4e38f;
#pragma unroll
    for (int j = 0; j < 8; ++j) {
        v[j] = lg[t + j * 256];
        m = fmaxf(m, v[j]);
    }
#pragma unroll
    for (int d = 16; d; d >>= 1) m = fmaxf(m, __shfl_xor_sync(0xffffffff, m, d));
    if (lane == 0) red[w] = m;
    __syncthreads();
    m = red[0];
#pragma unroll
    for (int j = 1; j < 8; ++j) m = fmaxf(m, red[j]);

    float e[8];
    float lsum = 0.0f;
#pragma unroll
    for (int j = 0; j < 8; ++j) {
        e[j] = ex2((v[j] - m) * 1.4426950408889634f);
        lsum += e[j];
    }
#pragma unroll
    for (int d = 16; d; d >>= 1) lsum += __shfl_xor_sync(0xffffffff, lsum, d);
    __syncthreads();
    if (lane == 0) red[w] = lsum;
    __syncthreads();
    float tot = 0.0f;
#pragma unroll
    for (int j = 0; j < 8; ++j) tot += red[j];
    float inv = 1.0f / tot;

    float* o = out + ((size_t)n * 2 + 1) * Ll;
#pragma unroll
    for (int j = 0; j < 8; ++j) o[t + j * 256] = e[j] * inv;
}

// =====================================================================
extern "C" void kernel_launch(void* const* d_in, const int* in_sizes, int n_in,
                              void* d_out, int out_size) {
    const float* encoder_input  = (const float*)d_in[0];
    const float* encoder_output = (const float*)d_in[1];
    const float* state          = (const float*)d_in[2];
    const float* W_ih           = (const float*)d_in[3];
    const float* W_hh           = (const float*)d_in[4];
    const float* b_ih           = (const float*)d_in[5];
    const float* b_hh           = (const float*)d_in[6];
    const float* Wq             = (const float*)d_in[7];
    const float* Wk             = (const float*)d_in[8];
    const float* w_score        = (const float*)d_in[9];
    float* out = (float*)d_out;

    cudaFuncSetAttribute(logits_k_kernel, cudaFuncAttributeMaxDynamicSharedMemorySize,
                         SMEM_TOTAL);
    int nsm = 148;
    cudaDeviceGetAttribute(&nsm, cudaDevAttrMultiProcessorCount, 0);

    // step 0: GRU -> q0 ; GEMM once (writes k fp16) + step-1 logits ; softmax+argmax
    gru_q_kernel<<<Nn / 4, 128>>>(encoder_input, state, W_ih, W_hh, b_ih, b_hh, Wq, 0);
    logits_k_kernel<<<nsm, 256, SMEM_TOTAL>>>(encoder_output, Wk, w_score);
    softmax_kernel<<<Nn, 256>>>(out, 0);
    // step 1: GRU(gathered input) -> q1 ; stream k + fused softmax
    gru_q_kernel<<<Nn / 4, 128>>>(encoder_input, state, W_ih, W_hh, b_ih, b_hh, Wq, 1);
    score2_kernel<<<Nn, 256>>>(out, w_score);
}